// round 4
// baseline (speedup 1.0000x reference)
#include <cuda_runtime.h>
#include <cuda_fp16.h>
#include <cstdint>

// CapsuleLayer dynamic routing on GB300 — u_hat never materialized (rank-8).
// B=128, U=8, C=2048, J=32, S=16, T=512. All GEMM operands fp16, L2-resident.
// 11 launches total: prep, then per-iter {softmax(fold) | sgemm | squash | pgemm}.

#define Bsz 128
#define Uu  8
#define Cc  2048
#define Jj  32
#define Ss  16
#define Tt  512

// ---- scratch (__device__, no allocs) ----
__device__ __half g_Wh [(size_t)Uu * Tt * Cc];     // [u][t][c] 16 MB
__device__ __half g_Xbc[(size_t)Uu * Bsz * Cc];    // [u][b][c]  4 MB
__device__ __half g_Xcb[(size_t)Uu * Cc * Bsz];    // [u][c][b]  4 MB
__device__ __half g_cwh[(size_t)Jj * Cc];          // [j][c] softmax weights
__device__ __half g_vh [(size_t)Tt * Bsz];         // [t][b]
__device__ float  g_spart[(size_t)16 * Bsz * Tt];  // 16 K-slices of s (4 MB)
__device__ float  g_bpart[(size_t)32 * Cc * 8];    // slice=(ttile*8+u) x [c][jl]
__device__ float  g_b[Cc * Jj];

#define MMA16816(d, A0, A1, A2, A3, B0, B1)                                   \
  asm volatile(                                                               \
      "mma.sync.aligned.m16n8k16.row.col.f32.f16.f16.f32 "                    \
      "{%0,%1,%2,%3},{%4,%5,%6,%7},{%8,%9},{%0,%1,%2,%3};"                    \
      : "+f"(d[0]), "+f"(d[1]), "+f"(d[2]), "+f"(d[3])                        \
      : "r"(A0), "r"(A1), "r"(A2), "r"(A3), "r"(B0), "r"(B1))

#define LDSM4(r0, r1, r2, r3, a)                                              \
  asm volatile("ldmatrix.sync.aligned.m8n8.x4.shared.b16 {%0,%1,%2,%3}, [%4];"\
               : "=r"(r0), "=r"(r1), "=r"(r2), "=r"(r3) : "r"(a))

static __device__ __forceinline__ uint32_t s2u(const void* p) {
    return (uint32_t)__cvta_generic_to_shared(p);
}

// ---------------------------------------------------------------------------
// Combined prep (one launch):
//  blocks [0,512):    Wh[u][t][c] = half(W[c][t][u])      (smem transpose)
//  blocks [512,640):  Xcb[u][c][b] = half(x[b][u][c])     (smem transpose)
//  blocks [640,896):  Xbc[u][b][c] = half(x[b][u][c])     (permute)
//  blocks [896,928):  cwh = 1/2048 (iter-0 softmax of b=0), zero g_b
//                     (FULL coverage: 1024 u32 + 2048 floats per block)
// ---------------------------------------------------------------------------
__global__ void __launch_bounds__(256) k_prep(const float* __restrict__ x,
                                              const float* __restrict__ W) {
    __shared__ __half buf[128 * 130];
    int r = blockIdx.x, tid = threadIdx.x;
    if (r < 512) {                                   // ---- W transpose
        int c0 = (r & 15) * 128, t0 = (r >> 4) * 16;
#pragma unroll
        for (int l = 0; l < 16; ++l) {
            int idx4 = tid + l * 256;                // 4096 float4
            int c = idx4 >> 5, f = (idx4 & 31) * 4;
            float4 v = *reinterpret_cast<const float4*>(
                W + (size_t)(c0 + c) * (Tt * Uu) + t0 * Uu + f);
            __half* row = buf + c * 130;
            row[f + 0] = __float2half_rn(v.x);
            row[f + 1] = __float2half_rn(v.y);
            row[f + 2] = __float2half_rn(v.z);
            row[f + 3] = __float2half_rn(v.w);
        }
        __syncthreads();
#pragma unroll
        for (int l = 0; l < 64; ++l) {
            int idx = tid + l * 256;                 // 16384
            int oc = idx & 127, orow = idx >> 7;
            int u = orow >> 4, tt = orow & 15;
            g_Wh[((size_t)u * Tt + t0 + tt) * Cc + c0 + oc] =
                buf[oc * 130 + tt * Uu + u];
        }
    } else if (r < 640) {                            // ---- Xcb transpose
        int i = r - 512;
        int u = i >> 4, c0 = (i & 15) * 128;
#pragma unroll
        for (int l = 0; l < 16; ++l) {
            int idx4 = tid + l * 256;
            int b = idx4 >> 5, cc = (idx4 & 31) * 4;
            float4 v = *reinterpret_cast<const float4*>(
                x + ((size_t)b * Uu + u) * Cc + c0 + cc);
            __half* row = buf + b * 130;
            row[cc + 0] = __float2half_rn(v.x);
            row[cc + 1] = __float2half_rn(v.y);
            row[cc + 2] = __float2half_rn(v.z);
            row[cc + 3] = __float2half_rn(v.w);
        }
        __syncthreads();
#pragma unroll
        for (int l = 0; l < 64; ++l) {
            int idx = tid + l * 256;
            int bb = idx & 127, cr = idx >> 7;
            g_Xcb[((size_t)u * Cc + c0 + cr) * Bsz + bb] = buf[bb * 130 + cr];
        }
    } else if (r < 896) {                            // ---- Xbc permute
        int i = r - 640;
#pragma unroll
        for (int l = 0; l < 8; ++l) {
            int g = l * 65536 + i * 256 + tid;       // 512K float4
            int c4 = (g & 511) * 4, rest = g >> 9;   // rest = b*8+u
            int b = rest >> 3, u = rest & 7;
            float4 v = *reinterpret_cast<const float4*>(x + (size_t)rest * Cc + c4);
            __half2 h0 = __floats2half2_rn(v.x, v.y);
            __half2 h1 = __floats2half2_rn(v.z, v.w);
            uint2 o = {*reinterpret_cast<uint32_t*>(&h0),
                       *reinterpret_cast<uint32_t*>(&h1)};
            *reinterpret_cast<uint2*>(&g_Xbc[((size_t)u * Bsz + b) * Cc + c4]) = o;
        }
    } else {                                         // ---- cwh=1/2048, b=0
        int i = r - 896;                             // 0..31
        __half h = __float2half_rn(1.0f / 2048.0f);
        __half2 hh = __halves2half2(h, h);
        uint32_t pat = *reinterpret_cast<uint32_t*>(&hh);
        // g_cwh: 32768 u32 total = 32 blocks x 1024
#pragma unroll
        for (int l = 0; l < 4; ++l)
            reinterpret_cast<uint32_t*>(g_cwh)[i * 1024 + l * 256 + tid] = pat;
        // g_b: 65536 floats total = 32 blocks x 2048
#pragma unroll
        for (int l = 0; l < 8; ++l)
            g_b[i * 2048 + l * 256 + tid] = 0.0f;
    }
}

// ---------------------------------------------------------------------------
// softmax over C per j, with fused b-update fold:
//   b[c,j] (+)= (1/B) sum_u g_bpart[(tt*8+u)][c][jl];  then cwh[j][c]=softmax.
// ---------------------------------------------------------------------------
__global__ void __launch_bounds__(256) k_softmax(int first) {
    int j = blockIdx.x, t = threadIdx.x;
    int tt = j >> 3, jl = j & 7;
    __shared__ float red[256];
    float bv[8];
#pragma unroll
    for (int i = 0; i < 8; ++i) {
        int c = t + i * 256;
        float s = first ? 0.0f : g_b[c * Jj + j];
        float d = 0.0f;
#pragma unroll
        for (int u = 0; u < Uu; ++u)
            d += g_bpart[((size_t)(tt * 8 + u) * Cc + c) * 8 + jl];
        s += d * (1.0f / Bsz);
        bv[i] = s;
        g_b[c * Jj + j] = s;
    }
    float m = bv[0];
#pragma unroll
    for (int i = 1; i < 8; ++i) m = fmaxf(m, bv[i]);
    red[t] = m; __syncthreads();
    for (int o = 128; o > 0; o >>= 1) {
        if (t < o) red[t] = fmaxf(red[t], red[t + o]);
        __syncthreads();
    }
    m = red[0]; __syncthreads();
    float sum = 0.0f;
#pragma unroll
    for (int i = 0; i < 8; ++i) { bv[i] = expf(bv[i] - m); sum += bv[i]; }
    red[t] = sum; __syncthreads();
    for (int o = 128; o > 0; o >>= 1) {
        if (t < o) red[t] += red[t + o];
        __syncthreads();
    }
    float inv = 1.0f / red[0];
#pragma unroll
    for (int i = 0; i < 8; ++i)
        g_cwh[(size_t)j * Cc + t + i * 256] = __float2half_rn(bv[i] * inv);
}

// ---------------------------------------------------------------------------
// GEMM1: s[b][t] = sum_{u,c} Xbc[u][b][c] * (cw[j(t)][c]*Wh[u][t][c]).
// grid (2,4,16) = 128 blocks (single wave); z: u=z>>1, c-half=z&1; K=1024/block.
// 8 warps = 4m x 2n; tiles 64b x 128t. ldmatrix + mma.m16n8k16.
// ---------------------------------------------------------------------------
__global__ void __launch_bounds__(256) k_sgemm() {
    __shared__ __half As[64 * 72];      // [b-local][c-local]
    __shared__ __half Bs[128 * 72];     // [t-local][c-local] cw-weighted
    int tid = threadIdx.x, lane = tid & 31, w = tid >> 5;
    int wm = w & 3, wn = w >> 2;
    int b0 = blockIdx.x * 64, t0 = blockIdx.y * 128;
    int z = blockIdx.z, u = z >> 1, c0 = (z & 1) * 1024;

    float acc[8][4];
#pragma unroll
    for (int i = 0; i < 8; ++i)
#pragma unroll
        for (int q = 0; q < 4; ++q) acc[i][q] = 0.0f;

    uint32_t aBase = s2u(As) +
        ((wm * 16 + (lane & 15)) * 72 + (lane >> 4) * 8) * 2;
    uint32_t bBase = s2u(Bs) +
        ((wn * 64 + (lane >> 4) * 8 + (lane & 7)) * 72 + ((lane >> 3) & 1) * 8) * 2;

    for (int kc = 0; kc < 16; ++kc) {
        int cb = c0 + kc * 64;
#pragma unroll
        for (int l = 0; l < 2; ++l) {            // A: 512 int4
            int idx = tid + l * 256;
            int rr = idx >> 3, k8 = (idx & 7) * 8;
            *reinterpret_cast<int4*>(&As[rr * 72 + k8]) =
                *reinterpret_cast<const int4*>(
                    &g_Xbc[((size_t)u * Bsz + b0 + rr) * Cc + cb + k8]);
        }
#pragma unroll
        for (int l = 0; l < 4; ++l) {            // B: 1024 int4, cw-weighted
            int idx = tid + l * 256;
            int rr = idx >> 3, k8 = (idx & 7) * 8;
            int tg = t0 + rr, j = tg >> 4;
            int4 wv = *reinterpret_cast<const int4*>(
                &g_Wh[((size_t)u * Tt + tg) * Cc + cb + k8]);
            int4 cv = *reinterpret_cast<const int4*>(
                &g_cwh[(size_t)j * Cc + cb + k8]);
            __half2* wp = reinterpret_cast<__half2*>(&wv);
            const __half2* cp = reinterpret_cast<const __half2*>(&cv);
#pragma unroll
            for (int q = 0; q < 4; ++q) wp[q] = __hmul2(wp[q], cp[q]);
            *reinterpret_cast<int4*>(&Bs[rr * 72 + k8]) = wv;
        }
        __syncthreads();
#pragma unroll
        for (int ks = 0; ks < 4; ++ks) {
            uint32_t kB = ks * 32;               // 16 halves = 32 bytes
            uint32_t a0, a1, a2, a3;
            LDSM4(a0, a1, a2, a3, aBase + kB);
#pragma unroll
            for (int p = 0; p < 4; ++p) {
                uint32_t r0, r1, r2, r3;
                LDSM4(r0, r1, r2, r3, bBase + p * 2304 + kB);  // p*16 rows
                MMA16816(acc[2 * p],     a0, a1, a2, a3, r0, r1);
                MMA16816(acc[2 * p + 1], a0, a1, a2, a3, r2, r3);
            }
        }
        __syncthreads();
    }
    int rrow = b0 + wm * 16 + (lane >> 2);
    float* base = g_spart + (size_t)z * (Bsz * Tt);
#pragma unroll
    for (int nf = 0; nf < 8; ++nf) {
        int col = t0 + wn * 64 + nf * 8 + (lane & 3) * 2;
        float* p = base + rrow * Tt + col;
        p[0] = acc[nf][0]; p[1] = acc[nf][1];
        p[8 * Tt] = acc[nf][2]; p[8 * Tt + 1] = acc[nf][3];
    }
}

// ---------------------------------------------------------------------------
// reduce 16 partial slices + squash (norm over J per (b,s) — faithful to ref).
// ---------------------------------------------------------------------------
__global__ void __launch_bounds__(Tt) k_squash(float* outp) {
    int b = blockIdx.x, t = threadIdx.x;
    float s = 0.0f;
#pragma unroll
    for (int sl = 0; sl < 16; ++sl)
        s += g_spart[(size_t)sl * (Bsz * Tt) + b * Tt + t];
    __shared__ float sv[Tt];
    sv[t] = s; __syncthreads();
    int si = t & (Ss - 1);
    float msq = 0.0f;
#pragma unroll
    for (int j = 0; j < Jj; ++j) { float vv = sv[j * Ss + si]; msq += vv * vv; }
    float mag = sqrtf(msq);
    float v = s * (msq / (1.0f + msq) / mag);
    g_vh[(size_t)t * Bsz + b] = __float2half_rn(v);
    if (outp) outp[b * Tt + t] = v;
}

// ---------------------------------------------------------------------------
// GEMM2 + fused b-reduce: P[c][t] = sum_b Xcb[u][c][b]*v[b][t];
// bpart[slice][c][jl] = sum_{t in j} Wh[u][t][c]*P[c][t]  (epilogue W via LDG).
// grid (16,4,4) = 256 blocks; 2 u per block; tiles 128c x 128t, K=128 (2x64).
// ---------------------------------------------------------------------------
__global__ void __launch_bounds__(256) k_pgemm() {
    __shared__ __half As[128 * 72];     // [c-local][b-chunk]
    __shared__ __half Bs[128 * 72];     // [t-local][b-chunk]
    int tid = threadIdx.x, lane = tid & 31, w = tid >> 5;
    int c0 = blockIdx.x * 128, t0 = blockIdx.y * 128;

    uint32_t aBase = s2u(As) +
        ((w * 16 + (lane & 15)) * 72 + (lane >> 4) * 8) * 2;
    uint32_t bBase = s2u(Bs) +
        (((lane >> 4) * 8 + (lane & 7)) * 72 + ((lane >> 3) & 1) * 8) * 2;
    int ccA = w * 16 + (lane >> 2);     // local c of acc rows 0-7
    int tlb = (lane & 3) * 2;

#pragma unroll
    for (int ui = 0; ui < 2; ++ui) {
        int u = blockIdx.z * 2 + ui;
        float acc[16][4];
#pragma unroll
        for (int i = 0; i < 16; ++i)
#pragma unroll
            for (int q = 0; q < 4; ++q) acc[i][q] = 0.0f;

#pragma unroll
        for (int chunk = 0; chunk < 2; ++chunk) {
            int kb = chunk * 64;
#pragma unroll
            for (int l = 0; l < 4; ++l) {        // A + B: 1024 int4 each
                int idx = tid + l * 256;
                int rr = idx >> 3, k8 = (idx & 7) * 8;
                *reinterpret_cast<int4*>(&As[rr * 72 + k8]) =
                    *reinterpret_cast<const int4*>(
                        &g_Xcb[((size_t)u * Cc + c0 + rr) * Bsz + kb + k8]);
                *reinterpret_cast<int4*>(&Bs[rr * 72 + k8]) =
                    *reinterpret_cast<const int4*>(
                        &g_vh[(size_t)(t0 + rr) * Bsz + kb + k8]);
            }
            __syncthreads();
#pragma unroll
            for (int ks = 0; ks < 4; ++ks) {
                uint32_t kB = ks * 32;
                uint32_t a0, a1, a2, a3;
                LDSM4(a0, a1, a2, a3, aBase + kB);
#pragma unroll
                for (int p = 0; p < 8; ++p) {
                    uint32_t r0, r1, r2, r3;
                    LDSM4(r0, r1, r2, r3, bBase + p * 2304 + kB);
                    MMA16816(acc[2 * p],     a0, a1, a2, a3, r0, r1);
                    MMA16816(acc[2 * p + 1], a0, a1, a2, a3, r2, r3);
                }
            }
            __syncthreads();
        }

        // epilogue: weighted reduce over t within each j; W read from L2.
        float baccA[8], baccB[8];
#pragma unroll
        for (int k = 0; k < 8; ++k) { baccA[k] = 0.0f; baccB[k] = 0.0f; }
#pragma unroll
        for (int nf = 0; nf < 16; ++nf) {
            int tl = nf * 8 + tlb;
            const __half* wp =
                g_Wh + ((size_t)u * Tt + t0 + tl) * Cc + c0;
            float w00 = __half2float(wp[ccA]);
            float w01 = __half2float(wp[Cc + ccA]);
            float w10 = __half2float(wp[ccA + 8]);
            float w11 = __half2float(wp[Cc + ccA + 8]);
            int jl = nf >> 1;
            baccA[jl] += acc[nf][0] * w00 + acc[nf][1] * w01;
            baccB[jl] += acc[nf][2] * w10 + acc[nf][3] * w11;
        }
#pragma unroll
        for (int k = 0; k < 8; ++k) {
            baccA[k] += __shfl_xor_sync(0xffffffffu, baccA[k], 1);
            baccA[k] += __shfl_xor_sync(0xffffffffu, baccA[k], 2);
            baccB[k] += __shfl_xor_sync(0xffffffffu, baccB[k], 1);
            baccB[k] += __shfl_xor_sync(0xffffffffu, baccB[k], 2);
        }
        if ((lane & 3) == 0) {
            int slice = blockIdx.y * 8 + u;
            float* pA = g_bpart + ((size_t)slice * Cc + c0 + ccA) * 8;
            float* pB = g_bpart + ((size_t)slice * Cc + c0 + ccA + 8) * 8;
#pragma unroll
            for (int jl = 0; jl < 8; ++jl) { pA[jl] = baccA[jl]; pB[jl] = baccB[jl]; }
        }
        __syncthreads();
    }
}

// ---------------------------------------------------------------------------
extern "C" void kernel_launch(void* const* d_in, const int* in_sizes, int n_in,
                              void* d_out, int out_size) {
    const float* x;
    const float* W;
    if (in_sizes[0] == Bsz * Uu * Cc) { x = (const float*)d_in[0]; W = (const float*)d_in[1]; }
    else                              { x = (const float*)d_in[1]; W = (const float*)d_in[0]; }
    float* out = (float*)d_out;

    k_prep<<<928, 256>>>(x, W);
    for (int it = 0; it < 3; ++it) {
        if (it > 0) k_softmax<<<Jj, 256>>>(it == 1 ? 1 : 0);
        k_sgemm<<<dim3(2, 4, 16), 256>>>();
        k_squash<<<Bsz, Tt>>>(it == 2 ? out : nullptr);
        if (it < 2) k_pgemm<<<dim3(16, 4, 4), 256>>>();
    }
}